// round 9
// baseline (speedup 1.0000x reference)
#include <cuda_runtime.h>

// ---------------------------------------------------------------------------
// Fused 3-layer tanh RNN + FC head.  B=8192, T=80, D=32, H=64.
// CTA = 64 batch, 256 threads (8 warps), grid = 128.
//
// v4: hidden states and x stored BATCH-DUPLICATED in smem as u64 {h,h}.
// Lane tile = 2 batches x 8 j.  Per k per lane:
//   1x LDS.128  -> {h_b,h_b,h_b+1,h_b+1}  (the two dup'd FMA2 operands, 0 MOVs)
//   2x LDS.128  -> w[j..j+7] as 4 natural j-pairs
//   8x FMA2     -> acc[2 b][4 j-pairs]
// = 11 issues, 3 smem wavefronts, 8 FMA2 per warp per k
// (fma pipe is the single bottleneck; issue 69%, crossbar 75% at the floor).
// Time loop is warp-private in batch -> __syncwarp only (v3 insight kept).
// ---------------------------------------------------------------------------

typedef unsigned long long u64;

#define B_TOT    8192
#define T_STEPS  80
#define D_IN     32
#define HDIM     64
#define BT       64
#define NTHREADS 256
#define PU       66          // dup'd-array row pitch in u64 (64 + 2 pad, 16B aligned)
#define PW       68          // weight row pitch in floats

// ---- u64 region: dup'd x + h arrays ----------------------------------------
#define U_X    0                       // 32 rows
#define U_H0   (U_X  + D_IN * PU)      // 64 rows
#define U_H1   (U_H0 + HDIM * PU)
#define U_H2   (U_H1 + HDIM * PU)
#define U_END  (U_H2 + HDIM * PU)      // 14784 u64 = 118272 B

// ---- float region: weights (k-major, transposed) + biases -------------------
#define FB      (U_END * 2)
#define F_WIH0  (FB)
#define F_WHH0  (F_WIH0 + D_IN * PW)
#define F_WIH1  (F_WHH0 + HDIM * PW)
#define F_WHH1  (F_WIH1 + HDIM * PW)
#define F_WIH2  (F_WHH1 + HDIM * PW)
#define F_WHH2  (F_WIH2 + HDIM * PW)
#define F_BS    (F_WHH2 + HDIM * PW)   // 3 x 64 combined biases
#define F_WFC   (F_BS   + 3 * HDIM)
#define F_BFC   (F_WFC  + HDIM)
#define SMEM_FLOATS (F_BFC + 1)
#define SMEM_BYTES  (SMEM_FLOATS * 4)  // 215044 B < 232448 B limit

// ---- packed fp32x2 helpers --------------------------------------------------
__device__ __forceinline__ u64 dup2f(float v) {
    u64 r;
    asm("mov.b64 %0, {%1, %1};" : "=l"(r) : "f"(v));
    return r;
}
__device__ __forceinline__ float2 unpack2(u64 v) {
    float2 r;
    asm("mov.b64 {%0, %1}, %2;" : "=f"(r.x), "=f"(r.y) : "l"(v));
    return r;
}
#define FMA2(accv, av, bv) \
    asm("fma.rn.f32x2 %0, %1, %2, %0;" : "+l"(accv) : "l"(av), "l"(bv))

// ---- K-reduction ------------------------------------------------------------
// inD: dup'd input, pre-offset to lane's batch pair (u64 index).
// WT:  weights, pre-offset to lane's j-octet (float index).
template <int K>
__device__ __forceinline__ void accum(const u64* __restrict__ inD,
                                      const float* __restrict__ WT,
                                      u64 acc[2][4]) {
#pragma unroll 16
    for (int k = 0; k < K; ++k) {
        ulonglong2 h  = *reinterpret_cast<const ulonglong2*>(inD + k * PU);
        ulonglong2 wa = *reinterpret_cast<const ulonglong2*>(WT + k * PW);
        ulonglong2 wb = *reinterpret_cast<const ulonglong2*>(WT + k * PW + 4);
        FMA2(acc[0][0], h.x, wa.x); FMA2(acc[0][1], h.x, wa.y);
        FMA2(acc[0][2], h.x, wb.x); FMA2(acc[0][3], h.x, wb.y);
        FMA2(acc[1][0], h.y, wa.x); FMA2(acc[1][1], h.y, wa.y);
        FMA2(acc[1][2], h.y, wb.x); FMA2(acc[1][3], h.y, wb.y);
    }
}

// ---- one RNN layer step (warp-private in batch) ----------------------------
template <int KIN>
__device__ __forceinline__ void layer_step(const u64* __restrict__ inD,
                                           const float* __restrict__ WinT,
                                           u64* __restrict__ hD,
                                           const float* __restrict__ WhhT,
                                           const float* __restrict__ bs,
                                           int bidx, int jcol) {
    u64 acc[2][4];
    ulonglong2 bv0 = *reinterpret_cast<const ulonglong2*>(bs + jcol);
    ulonglong2 bv1 = *reinterpret_cast<const ulonglong2*>(bs + jcol + 4);
    acc[0][0] = bv0.x; acc[0][1] = bv0.y; acc[0][2] = bv1.x; acc[0][3] = bv1.y;
    acc[1][0] = bv0.x; acc[1][1] = bv0.y; acc[1][2] = bv1.x; acc[1][3] = bv1.y;

    accum<KIN>(inD + bidx, WinT + jcol, acc);   // input projection
    accum<HDIM>(hD + bidx, WhhT + jcol, acc);   // recurrence (reads old h)

    __syncwarp();   // lane-crossed reads of old h done before overwrite

#pragma unroll
    for (int p = 0; p < 4; ++p) {
        float2 a0 = unpack2(acc[0][p]);   // batch b : j = jcol+2p, jcol+2p+1
        float2 a1 = unpack2(acc[1][p]);   // batch b+1
        float t00 = tanhf(a0.x), t01 = tanhf(a0.y);
        float t10 = tanhf(a1.x), t11 = tanhf(a1.y);
        ulonglong2 s0, s1;
        s0.x = dup2f(t00); s0.y = dup2f(t10);
        s1.x = dup2f(t01); s1.y = dup2f(t11);
        *reinterpret_cast<ulonglong2*>(hD + (jcol + 2 * p) * PU + bidx)     = s0;
        *reinterpret_cast<ulonglong2*>(hD + (jcol + 2 * p + 1) * PU + bidx) = s1;
    }

    __syncwarp();   // new h visible to all lanes of this warp
}

// ---- transpose weight [64][K] row-major -> WT[k*PW + j] --------------------
__device__ __forceinline__ void load_wT(const float* __restrict__ W,
                                        float* __restrict__ WT, int K, int tid) {
    for (int idx = tid; idx < HDIM * K; idx += NTHREADS) {
        int j = idx / K;
        int k = idx - j * K;
        WT[k * PW + j] = W[idx];
    }
}

__global__ void __launch_bounds__(NTHREADS, 1)
rnn_fused_v4(const float* __restrict__ x,
             const float* __restrict__ Wih0, const float* __restrict__ Whh0,
             const float* __restrict__ bih0, const float* __restrict__ bhh0,
             const float* __restrict__ Wih1, const float* __restrict__ Whh1,
             const float* __restrict__ bih1, const float* __restrict__ bhh1,
             const float* __restrict__ Wih2, const float* __restrict__ Whh2,
             const float* __restrict__ bih2, const float* __restrict__ bhh2,
             const float* __restrict__ Wfc,  const float* __restrict__ bfc,
             float* __restrict__ out) {
    extern __shared__ __align__(16) float smem[];
    u64* smemu = reinterpret_cast<u64*>(smem);
    const int tid   = threadIdx.x;
    const int bbase = blockIdx.x * BT;

    // ---- one-time setup -----------------------------------------------------
    load_wT(Wih0, smem + F_WIH0, D_IN, tid);
    load_wT(Whh0, smem + F_WHH0, HDIM, tid);
    load_wT(Wih1, smem + F_WIH1, HDIM, tid);
    load_wT(Whh1, smem + F_WHH1, HDIM, tid);
    load_wT(Wih2, smem + F_WIH2, HDIM, tid);
    load_wT(Whh2, smem + F_WHH2, HDIM, tid);
    if (tid < 3 * HDIM) {
        int l = tid >> 6, j = tid & 63;
        const float* bi = (l == 0) ? bih0 : (l == 1) ? bih1 : bih2;
        const float* bh = (l == 0) ? bhh0 : (l == 1) ? bhh1 : bhh2;
        smem[F_BS + tid] = bi[j] + bh[j];
    }
    if (tid < HDIM) smem[F_WFC + tid] = Wfc[tid];
    if (tid == 0)   smem[F_BFC] = bfc[0];
    // zero dup'd hidden-state arrays
    for (int i = tid; i < 3 * HDIM * PU; i += NTHREADS) smemu[U_H0 + i] = 0ULL;

    // ---- x prefetch: thread owns 8 consecutive floats of one (b,t) row ------
    // (warp-private: warp w's threads cover exactly batches w*8..w*8+7)
    const int xb = tid >> 2;            // local batch 0..63
    const int xd = (tid & 3) * 8;       // d offset 0,8,16,24
    const float* xp = x + (size_t)(bbase + xb) * (T_STEPS * D_IN) + xd;
    float4 xr0 = *reinterpret_cast<const float4*>(xp);
    float4 xr1 = *reinterpret_cast<const float4*>(xp + 4);

    __syncthreads();   // setup visible to all warps

    const int lane = tid & 31;
    const int warp = tid >> 5;
    const int jo   = lane & 7;          // j-octet
    const int bp   = lane >> 3;         // batch pair within warp
    const int bidx = warp * 8 + bp * 2; // u64 column index (= batch index)
    const int jcol = jo * 8;            // lane's first j

    const float* bs0 = smem + F_BS;
    const float* bs1 = smem + F_BS + HDIM;
    const float* bs2 = smem + F_BS + 2 * HDIM;

    for (int t = 0; t < T_STEPS; ++t) {
        // stage x_t dup'd (xD[d][b] = {x,x}); prefetch x_{t+1}
        u64* xc = smemu + U_X + xb;
        xc[(xd + 0) * PU] = dup2f(xr0.x); xc[(xd + 1) * PU] = dup2f(xr0.y);
        xc[(xd + 2) * PU] = dup2f(xr0.z); xc[(xd + 3) * PU] = dup2f(xr0.w);
        xc[(xd + 4) * PU] = dup2f(xr1.x); xc[(xd + 5) * PU] = dup2f(xr1.y);
        xc[(xd + 6) * PU] = dup2f(xr1.z); xc[(xd + 7) * PU] = dup2f(xr1.w);
        if (t + 1 < T_STEPS) {
            xr0 = *reinterpret_cast<const float4*>(xp + (t + 1) * D_IN);
            xr1 = *reinterpret_cast<const float4*>(xp + (t + 1) * D_IN + 4);
        }
        __syncwarp();   // warp's x columns staged

        layer_step<D_IN>(smemu + U_X,  smem + F_WIH0, smemu + U_H0,
                         smem + F_WHH0, bs0, bidx, jcol);
        layer_step<HDIM>(smemu + U_H0, smem + F_WIH1, smemu + U_H1,
                         smem + F_WHH1, bs1, bidx, jcol);
        layer_step<HDIM>(smemu + U_H1, smem + F_WIH2, smemu + U_H2,
                         smem + F_WHH2, bs2, bidx, jcol);
    }

    __syncthreads();   // FC head reads h2 across warp boundaries

    // ---- FC head: out[b] = h2_last[b] . Wfc + bfc ---------------------------
    if (tid < BT) {
        float s = smem[F_BFC];
        const float* h2f = reinterpret_cast<const float*>(smemu + U_H2);
        const float* wf  = smem + F_WFC;
#pragma unroll
        for (int j = 0; j < HDIM; ++j)
            s += h2f[(j * PU + tid) * 2] * wf[j];
        out[bbase + tid] = s;
    }
}

extern "C" void kernel_launch(void* const* d_in, const int* in_sizes, int n_in,
                              void* d_out, int out_size) {
    (void)in_sizes; (void)n_in; (void)out_size;
    cudaFuncSetAttribute(rnn_fused_v4,
                         cudaFuncAttributeMaxDynamicSharedMemorySize,
                         SMEM_BYTES);
    rnn_fused_v4<<<B_TOT / BT, NTHREADS, SMEM_BYTES>>>(
        (const float*)d_in[0],
        (const float*)d_in[1],  (const float*)d_in[2],
        (const float*)d_in[3],  (const float*)d_in[4],
        (const float*)d_in[5],  (const float*)d_in[6],
        (const float*)d_in[7],  (const float*)d_in[8],
        (const float*)d_in[9],  (const float*)d_in[10],
        (const float*)d_in[11], (const float*)d_in[12],
        (const float*)d_in[13], (const float*)d_in[14],
        (float*)d_out);
}

// round 10
// speedup vs baseline: 2.5260x; 2.5260x over previous
#include <cuda_runtime.h>

// ---------------------------------------------------------------------------
// Fused 3-layer tanh RNN + FC head.  B=8192, T=80, D=32, H=64.
// CTA = 64 batch, 128 threads (4 warps), grid = 128.
//
// v5 = v3 dataflow (broadcast h loads, spread w loads, syncwarp-only loop)
// with DOUBLED batch per warp: warp = 16 batches x 64 j, lane = 16b x 2j.
// Per warp per k: 4 broadcast LDS.128 (h) + 1 spread LDS.64 (w) + 2 dup MOVs
// + 16 FMA2.  Per SMSP (1 warp): fma=32cyc (sole bottleneck), issue~25,
// crossbar 24/32 wf per SM.  Amortizes w-load + MOV + loop overhead 2x.
// ---------------------------------------------------------------------------

#define B_TOT    8192
#define T_STEPS  80
#define D_IN     32
#define HDIM     64
#define BT       64          // batch tile per CTA
#define NTHREADS 128
#define P        68          // smem row pitch in floats

// smem layout offsets (in floats)
#define OFF_X    0
#define OFF_H0   (OFF_X    + D_IN * P)
#define OFF_H1   (OFF_H0   + HDIM * P)
#define OFF_H2   (OFF_H1   + HDIM * P)
#define OFF_WIH0 (OFF_H2   + HDIM * P)
#define OFF_WHH0 (OFF_WIH0 + D_IN * P)
#define OFF_WIH1 (OFF_WHH0 + HDIM * P)
#define OFF_WHH1 (OFF_WIH1 + HDIM * P)
#define OFF_WIH2 (OFF_WHH1 + HDIM * P)
#define OFF_WHH2 (OFF_WIH2 + HDIM * P)
#define OFF_BS   (OFF_WHH2 + HDIM * P)   // 3 x 64 combined biases
#define OFF_WFC  (OFF_BS   + 3 * HDIM)
#define OFF_BFC  (OFF_WFC  + HDIM)
#define SMEM_FLOATS (OFF_BFC + 1)

typedef unsigned long long u64;

// ---- packed fp32x2 helpers --------------------------------------------------
__device__ __forceinline__ u64 dup2(float v) {
    u64 r;
    asm("mov.b64 %0, {%1, %1};" : "=l"(r) : "f"(v));
    return r;
}
__device__ __forceinline__ float2 unpack2(u64 v) {
    float2 r;
    asm("mov.b64 {%0, %1}, %2;" : "=f"(r.x), "=f"(r.y) : "l"(v));
    return r;
}
#define FMA2(accv, av, bv) \
    asm("fma.rn.f32x2 %0, %1, %2, %0;" : "+l"(accv) : "l"(av), "l"(bv))

// ---- outer-product accumulate: acc[i][jj] += inT[k][b0+2i..] * WT[k][j0+jj]
// warp covers 16 batches (8 b-pairs), lane covers 2 j.
template <int K>
__device__ __forceinline__ void accum(const float* __restrict__ inT,
                                      const float* __restrict__ WT,
                                      int b0, int j0,
                                      u64 acc[8][2]) {
#pragma unroll 16
    for (int k = 0; k < K; ++k) {
        // 16 batch values, 4 broadcast LDS.128 (warp-uniform addresses)
        double2 ha = *reinterpret_cast<const double2*>(inT + k * P + b0);
        double2 hb = *reinterpret_cast<const double2*>(inT + k * P + b0 + 4);
        double2 hc = *reinterpret_cast<const double2*>(inT + k * P + b0 + 8);
        double2 hd = *reinterpret_cast<const double2*>(inT + k * P + b0 + 12);
        // lane's 2 weights (spread LDS.64), duplicated into both f32x2 halves
        float2 wv = *reinterpret_cast<const float2*>(WT + k * P + j0);
        u64 w0 = dup2(wv.x);
        u64 w1 = dup2(wv.y);
        u64 h0 = __double_as_longlong(ha.x), h1 = __double_as_longlong(ha.y);
        u64 h2 = __double_as_longlong(hb.x), h3 = __double_as_longlong(hb.y);
        u64 h4 = __double_as_longlong(hc.x), h5 = __double_as_longlong(hc.y);
        u64 h6 = __double_as_longlong(hd.x), h7 = __double_as_longlong(hd.y);
        FMA2(acc[0][0], h0, w0); FMA2(acc[0][1], h0, w1);
        FMA2(acc[1][0], h1, w0); FMA2(acc[1][1], h1, w1);
        FMA2(acc[2][0], h2, w0); FMA2(acc[2][1], h2, w1);
        FMA2(acc[3][0], h3, w0); FMA2(acc[3][1], h3, w1);
        FMA2(acc[4][0], h4, w0); FMA2(acc[4][1], h4, w1);
        FMA2(acc[5][0], h5, w0); FMA2(acc[5][1], h5, w1);
        FMA2(acc[6][0], h6, w0); FMA2(acc[6][1], h6, w1);
        FMA2(acc[7][0], h7, w0); FMA2(acc[7][1], h7, w1);
    }
}

// ---- one RNN layer step (warp-private in batch) -----------------------------
template <int KIN>
__device__ __forceinline__ void layer_step(const float* __restrict__ inT,
                                           const float* __restrict__ WinT,
                                           float* __restrict__ hT,
                                           const float* __restrict__ WhhT,
                                           const float* __restrict__ bs,
                                           int b0, int j0) {
    u64 acc[8][2];
    float2 bv = *reinterpret_cast<const float2*>(bs + j0);
    u64 bx = dup2(bv.x), by = dup2(bv.y);
#pragma unroll
    for (int i = 0; i < 8; ++i) { acc[i][0] = bx; acc[i][1] = by; }

    accum<KIN>(inT, WinT, b0, j0, acc);   // input projection
    accum<HDIM>(hT,  WhhT, b0, j0, acc);  // recurrence (reads old h)

    __syncwarp();  // lanes' reads of old hT done before overwrite

#pragma unroll
    for (int jj = 0; jj < 2; ++jj) {
        float* row = hT + (j0 + jj) * P + b0;
#pragma unroll
        for (int q = 0; q < 2; ++q) {       // two float4 groups of 8 batches
            float2 a0 = unpack2(acc[4 * q + 0][jj]);
            float2 a1 = unpack2(acc[4 * q + 1][jj]);
            float2 a2 = unpack2(acc[4 * q + 2][jj]);
            float2 a3 = unpack2(acc[4 * q + 3][jj]);
            *reinterpret_cast<float4*>(row + 8 * q) =
                make_float4(tanhf(a0.x), tanhf(a0.y), tanhf(a1.x), tanhf(a1.y));
            *reinterpret_cast<float4*>(row + 8 * q + 4) =
                make_float4(tanhf(a2.x), tanhf(a2.y), tanhf(a3.x), tanhf(a3.y));
        }
    }

    __syncwarp();  // new h visible to all lanes of this warp
}

// ---- transpose weight [64][K] row-major -> WT[k*P + j] ----------------------
__device__ __forceinline__ void load_wT(const float* __restrict__ W,
                                        float* __restrict__ WT, int K, int tid) {
    for (int idx = tid; idx < HDIM * K; idx += NTHREADS) {
        int j = idx / K;
        int k = idx - j * K;
        WT[k * P + j] = W[idx];
    }
}

__global__ void __launch_bounds__(NTHREADS, 1)
rnn_fused_v5(const float* __restrict__ x,
             const float* __restrict__ Wih0, const float* __restrict__ Whh0,
             const float* __restrict__ bih0, const float* __restrict__ bhh0,
             const float* __restrict__ Wih1, const float* __restrict__ Whh1,
             const float* __restrict__ bih1, const float* __restrict__ bhh1,
             const float* __restrict__ Wih2, const float* __restrict__ Whh2,
             const float* __restrict__ bih2, const float* __restrict__ bhh2,
             const float* __restrict__ Wfc,  const float* __restrict__ bfc,
             float* __restrict__ out) {
    extern __shared__ float smem[];
    const int tid   = threadIdx.x;
    const int bbase = blockIdx.x * BT;

    // ---- one-time setup -----------------------------------------------------
    load_wT(Wih0, smem + OFF_WIH0, D_IN, tid);
    load_wT(Whh0, smem + OFF_WHH0, HDIM, tid);
    load_wT(Wih1, smem + OFF_WIH1, HDIM, tid);
    load_wT(Whh1, smem + OFF_WHH1, HDIM, tid);
    load_wT(Wih2, smem + OFF_WIH2, HDIM, tid);
    load_wT(Whh2, smem + OFF_WHH2, HDIM, tid);
    {   // combined biases: 192 entries, 128 threads -> strided
        for (int i = tid; i < 3 * HDIM; i += NTHREADS) {
            int l = i >> 6, j = i & 63;
            const float* bi = (l == 0) ? bih0 : (l == 1) ? bih1 : bih2;
            const float* bh = (l == 0) ? bhh0 : (l == 1) ? bhh1 : bhh2;
            smem[OFF_BS + i] = bi[j] + bh[j];
        }
    }
    if (tid < HDIM) smem[OFF_WFC + tid] = Wfc[tid];
    if (tid == 0)   smem[OFF_BFC] = bfc[0];
    for (int i = tid; i < 3 * HDIM * P; i += NTHREADS) smem[OFF_H0 + i] = 0.0f;

    // ---- x prefetch: each thread owns 16 consecutive floats of one row ------
    // (warp-private: warp w's threads cover exactly batches w*16..w*16+15)
    const int xb = tid >> 1;            // local batch index 0..63
    const int xd = (tid & 1) * 16;      // d offset 0 or 16
    const float* xp = x + (size_t)(bbase + xb) * (T_STEPS * D_IN) + xd;
    float4 xr0 = *reinterpret_cast<const float4*>(xp);
    float4 xr1 = *reinterpret_cast<const float4*>(xp + 4);
    float4 xr2 = *reinterpret_cast<const float4*>(xp + 8);
    float4 xr3 = *reinterpret_cast<const float4*>(xp + 12);

    __syncthreads();   // setup visible to all warps

    const int lane = tid & 31;
    const int warp = tid >> 5;
    const int b0   = warp * 16;         // warp's batch sub-tile (16 wide)
    const int j0   = lane * 2;          // lane's hidden-unit pair

    for (int t = 0; t < T_STEPS; ++t) {
        // stage x_t into smem (transposed xT[d][b]); prefetch x_{t+1}
        float* xc = smem + OFF_X + xb;
        xc[(xd + 0)  * P] = xr0.x; xc[(xd + 1)  * P] = xr0.y;
        xc[(xd + 2)  * P] = xr0.z; xc[(xd + 3)  * P] = xr0.w;
        xc[(xd + 4)  * P] = xr1.x; xc[(xd + 5)  * P] = xr1.y;
        xc[(xd + 6)  * P] = xr1.z; xc[(xd + 7)  * P] = xr1.w;
        xc[(xd + 8)  * P] = xr2.x; xc[(xd + 9)  * P] = xr2.y;
        xc[(xd + 10) * P] = xr2.z; xc[(xd + 11) * P] = xr2.w;
        xc[(xd + 12) * P] = xr3.x; xc[(xd + 13) * P] = xr3.y;
        xc[(xd + 14) * P] = xr3.z; xc[(xd + 15) * P] = xr3.w;
        if (t + 1 < T_STEPS) {
            const float* xn = xp + (t + 1) * D_IN;
            xr0 = *reinterpret_cast<const float4*>(xn);
            xr1 = *reinterpret_cast<const float4*>(xn + 4);
            xr2 = *reinterpret_cast<const float4*>(xn + 8);
            xr3 = *reinterpret_cast<const float4*>(xn + 12);
        }
        __syncwarp();   // warp's x columns staged

        layer_step<D_IN>(smem + OFF_X,  smem + OFF_WIH0, smem + OFF_H0,
                         smem + OFF_WHH0, smem + OFF_BS,            b0, j0);
        layer_step<HDIM>(smem + OFF_H0, smem + OFF_WIH1, smem + OFF_H1,
                         smem + OFF_WHH1, smem + OFF_BS + HDIM,     b0, j0);
        layer_step<HDIM>(smem + OFF_H1, smem + OFF_WIH2, smem + OFF_H2,
                         smem + OFF_WHH2, smem + OFF_BS + 2 * HDIM, b0, j0);
    }

    __syncthreads();   // FC head reads h2 across warp boundaries

    // ---- FC head: out[b] = h2_last[b] . Wfc + bfc ---------------------------
    if (tid < BT) {
        float s = smem[OFF_BFC];
        const float* h2 = smem + OFF_H2;
        const float* wf = smem + OFF_WFC;
#pragma unroll
        for (int j = 0; j < HDIM; ++j) s += h2[j * P + tid] * wf[j];
        out[bbase + tid] = s;
    }
}

extern "C" void kernel_launch(void* const* d_in, const int* in_sizes, int n_in,
                              void* d_out, int out_size) {
    (void)in_sizes; (void)n_in; (void)out_size;
    const size_t smem_bytes = SMEM_FLOATS * sizeof(float);
    cudaFuncSetAttribute(rnn_fused_v5,
                         cudaFuncAttributeMaxDynamicSharedMemorySize,
                         (int)smem_bytes);
    rnn_fused_v5<<<B_TOT / BT, NTHREADS, smem_bytes>>>(
        (const float*)d_in[0],
        (const float*)d_in[1],  (const float*)d_in[2],
        (const float*)d_in[3],  (const float*)d_in[4],
        (const float*)d_in[5],  (const float*)d_in[6],
        (const float*)d_in[7],  (const float*)d_in[8],
        (const float*)d_in[9],  (const float*)d_in[10],
        (const float*)d_in[11], (const float*)d_in[12],
        (const float*)d_in[13], (const float*)d_in[14],
        (float*)d_out);
}